// round 13
// baseline (speedup 1.0000x reference)
#include <cuda_runtime.h>
#include <cuda_bf16.h>
#include <cstdint>

#define D   256
#define K   8192
#define BT  32768
#define NPAIR 128        // row-pairs of 256 rows (2 CTAs x 128)
#define NUNIT 512        // (pair, quarter) units
#define NCLUST 74
#define NCT_U 16         // ctiles per unit
#define NCH 4            // k-chunks of 64 per D=256
#define NSTAGE 4
#define NTHREADS 384
#define GLIM (NPAIR - 24)   // during-compute warp gathers stop here

#if defined(__CUDA_ARCH_FEAT_SM103_ALL) || defined(__CUDA_ARCH_FEAT_SM100_ALL) || defined(__CUDA_ARCH_SPECIFIC__)
#define VQ_TCGEN05 1
#else
#define VQ_TCGEN05 0
#endif

// ---- smem layout (bytes) ----
#define SM_A    0            // xh 64KB | xl 64KB (blocked SW128 image, this CTA's 128 rows)
#define SM_B    131072       // 4 stages x 16KB (ch 8KB | cl 8KB)
#define SM_CBN  196608       // 8192 codebook norms (32KB)
#define SM_RED  229376       // rv f32[128] | ri i32[128]
#define SM_ROWA 230400       // 128 floats
#define SM_BAR  230912
#define SM_TOT  231104

#define OFF_FULL(s)   (SM_BAR + (s)*8)
#define OFF_EMPTY(s)  (SM_BAR + 32 + (s)*8)
#define OFF_FULLX(s)  (SM_BAR + 64 + (s)*8)
#define OFF_DREADY(p) (SM_BAR + 96 + (p)*8)
#define OFF_EFREE(p)  (SM_BAR + 128 + (p)*8)
#define OFF_TPTR      (SM_BAR + 160)
#define OFF_AREADYX   (SM_BAR + 168)
#define OFF_TKT       (SM_BAR + 176)

// idesc: f32 accum, bf16 a/b, N=128, M=256 (cta_group::2)
#define IDESC2 0x10200490u

__device__ double g_sse;
__device__ float  g_cbnorm[K];
__device__ unsigned long long g_best[BT];
__device__ __align__(16) int g_done[NPAIR];   // 0..8 accumulating; 9 = claimed for gather
__device__ int    g_claimed;
__device__ int    g_gcnt;
__device__ unsigned char g_cb[(size_t)512 * 16384];   // [ctile][chunk][half][ch|cl] swizzled

// ================= helpers =================
__device__ __forceinline__ uint32_t smem_u32(const void* p) {
    uint32_t a;
    asm("{ .reg .u64 t; cvta.to.shared.u64 t, %1; cvt.u32.u64 %0, t; }" : "=r"(a) : "l"(p));
    return a;
}

__device__ __forceinline__ void split_pack8(const float* v, uint4& H, uint4& L, float& ss) {
    uint32_t hw[4], lw[4];
    #pragma unroll
    for (int k = 0; k < 4; k++) {
        float a = v[2 * k], b = v[2 * k + 1];
        ss = __fmaf_rn(a, a, ss); ss = __fmaf_rn(b, b, ss);
        __nv_bfloat16 ha = __float2bfloat16_rn(a);
        __nv_bfloat16 hb = __float2bfloat16_rn(b);
        float la = a - __bfloat162float(ha);
        float lb = b - __bfloat162float(hb);
        hw[k] = (uint32_t)__bfloat16_as_ushort(ha) | ((uint32_t)__bfloat16_as_ushort(hb) << 16);
        lw[k] = (uint32_t)__bfloat16_as_ushort(__float2bfloat16_rn(la))
              | ((uint32_t)__bfloat16_as_ushort(__float2bfloat16_rn(lb)) << 16);
    }
    H = make_uint4(hw[0], hw[1], hw[2], hw[3]);
    L = make_uint4(lw[0], lw[1], lw[2], lw[3]);
}

// warp-collective: scan g_done for a ready pair and CAS-claim it.
// returns pair id, -1 (none ready now), -2 (claim limit reached).
__device__ __forceinline__ int warp_scan_claim(int lane, int lim) {
    int cl_tot = 0;
    if (lane == 0) cl_tot = atomicAdd(&g_claimed, 0);
    cl_tot = __shfl_sync(0xffffffffu, cl_tot, 0);
    if (cl_tot >= lim) return -2;
    int4 v = __ldcg((const int4*)(g_done + lane * 4));
    int cand = -1;
    if      (v.x == 8) cand = lane * 4;
    else if (v.y == 8) cand = lane * 4 + 1;
    else if (v.z == 8) cand = lane * 4 + 2;
    else if (v.w == 8) cand = lane * 4 + 3;
    unsigned m = __ballot_sync(0xffffffffu, cand >= 0);
    int got = -1;
    while (m) {
        int src = __ffs(m) - 1;
        int p = __shfl_sync(0xffffffffu, cand, src);
        int ok = 0;
        if (lane == 0) ok = (atomicCAS(&g_done[p], 8, 9) == 8);
        ok = __shfl_sync(0xffffffffu, ok, 0);
        if (ok) { got = p; break; }
        m &= m - 1;
    }
    if (got >= 0 && lane == 0) atomicAdd(&g_claimed, 1);
    return __shfl_sync(0xffffffffu, got, 0);
}

// ========== output gather for one pair (256 rows) ==========
__device__ __forceinline__ void gather_pair(int pair, int tidx, int stride,
        const float* __restrict__ x, const float* __restrict__ cb,
        float* __restrict__ outq, float* __restrict__ outidx) {
    const int r0 = pair * 256;
    if (outidx)
        for (int r = tidx; r < 256; r += stride)
            outidx[r0 + r] = (float)(unsigned)(g_best[r0 + r] & 0xFFFFFFFFull);
    float sse = 0.f;
    float4* oq = (float4*)outq;
    const float4* cg = (const float4*)cb;
    const float4* xg = (const float4*)x;
    for (int i = tidx; i < 256 * 64; i += stride) {
        int r = r0 + (i >> 6), c = i & 63;
        unsigned idx = (unsigned)(g_best[r] & 0xFFFFFFFFull);
        float4 q  = cg[(size_t)idx * 64 + c];
        float4 xv = xg[(size_t)r * 64 + c];
        float dx = __fsub_rn(q.x, xv.x), dy = __fsub_rn(q.y, xv.y);
        float dz = __fsub_rn(q.z, xv.z), dw = __fsub_rn(q.w, xv.w);
        float4 o;
        o.x = __fadd_rn(xv.x, dx); o.y = __fadd_rn(xv.y, dy);
        o.z = __fadd_rn(xv.z, dz); o.w = __fadd_rn(xv.w, dw);
        oq[(size_t)r * 64 + c] = o;
        sse += dx * dx + dy * dy + dz * dz + dw * dw;
    }
    #pragma unroll
    for (int o = 16; o; o >>= 1) sse += __shfl_xor_sync(0xffffffffu, sse, o);
    if ((tidx & 31) == 0) atomicAdd(&g_sse, (double)sse);
}

__device__ __forceinline__ void gather_complete(float* outloss) {
    __threadfence();
    int old = atomicAdd(&g_gcnt, 1);
    if (old == NPAIR - 1 && outloss) {
        double s = atomicAdd(&g_sse, 0.0);
        *outloss = (float)((s / 8388608.0) * 1.25);
    }
}

#if VQ_TCGEN05
__device__ __forceinline__ uint32_t elect_one() {
    uint32_t p;
    asm volatile("{\n\t.reg .pred p;\n\telect.sync _|p, 0xFFFFFFFF;\n\tselp.b32 %0, 1, 0, p;\n\t}" : "=r"(p));
    return p;
}
__device__ __forceinline__ uint32_t ctarank() {
    uint32_t r; asm("mov.u32 %0, %%cluster_ctarank;" : "=r"(r)); return r;
}
#define MBAR_INIT(a, n) asm volatile("mbarrier.init.shared.b64 [%0], %1;" :: "r"(a), "r"(n) : "memory")
#define MBAR_EXPECT(a, b) asm volatile("mbarrier.arrive.expect_tx.shared.b64 _, [%0], %1;" :: "r"(a), "r"(b) : "memory")
#define MBAR_ARRIVE(a) asm volatile("mbarrier.arrive.shared.b64 _, [%0];" :: "r"(a) : "memory")
#define MBAR_ARRIVE_RANK0(a) \
    asm volatile("{\n\t.reg .b32 ra;\n\tmapa.shared::cluster.u32 ra, %0, %1;\n\t" \
        "mbarrier.arrive.shared::cluster.b64 _, [ra];\n\t}" :: "r"(a), "r"(0) : "memory")
#define MBAR_WAIT(a, ph) do {                                                      \
    uint32_t _m = (a), _p = (ph), _d;                                              \
    asm volatile("{\n\t.reg .pred p;\n\t"                                          \
        "mbarrier.try_wait.parity.acquire.cta.shared::cta.b64 p, [%1], %2;\n\t"    \
        "selp.b32 %0, 1, 0, p;\n\t}" : "=r"(_d) : "r"(_m), "r"(_p) : "memory");    \
    if (!_d) {                                                                     \
        asm volatile("{\n\t.reg .pred P1;\n\t"                                     \
        "WL_%=:\n\t"                                                               \
        "mbarrier.try_wait.parity.acquire.cta.shared::cta.b64 P1, [%0], %1, 0x989680;\n\t" \
        "@P1 bra.uni WD_%=;\n\tbra.uni WL_%=;\n\tWD_%=:\n\t}"                      \
        :: "r"(_m), "r"(_p) : "memory");                                           \
    }                                                                              \
} while (0)
#define TC_ALLOC2(sp, n) asm volatile("tcgen05.alloc.cta_group::2.sync.aligned.shared::cta.b32 [%0], %1;" :: "r"(sp), "r"(n) : "memory")
#define TC_RELINQ2() asm volatile("tcgen05.relinquish_alloc_permit.cta_group::2.sync.aligned;")
#define TC_DEALLOC2(t, n) asm volatile("tcgen05.dealloc.cta_group::2.sync.aligned.b32 %0, %1;" :: "r"(t), "r"(n))
#define TC_COMMIT_MC(a) \
    asm volatile("tcgen05.commit.cta_group::2.mbarrier::arrive::one.shared::cluster.multicast::cluster.b64 [%0], %1;" \
        :: "r"(a), "h"((unsigned short)0x3) : "memory")
#define TC_FENCE_AFTER() asm volatile("tcgen05.fence::after_thread_sync;" ::: "memory")
#define TC_WAIT_LD() asm volatile("tcgen05.wait::ld.sync.aligned;" ::: "memory")
#define FENCE_ASYNC() asm volatile("fence.proxy.async.shared::cta;" ::: "memory")
#define CLUSTER_SYNC() do { \
    asm volatile("barrier.cluster.arrive.aligned;" ::: "memory"); \
    asm volatile("barrier.cluster.wait.aligned;" ::: "memory"); } while (0)
#define BULK_CP(dst, src, bytes, mbar) \
    asm volatile("cp.async.bulk.shared::cta.global.mbarrier::complete_tx::bytes [%0], [%1], %2, [%3];" \
        :: "r"(dst), "l"(src), "r"(bytes), "r"(mbar) : "memory")
#define EPIBAR() asm volatile("bar.sync 1, 256;" ::: "memory")

static constexpr uint64_t DESC_BASE =
    (uint64_t(2) << 61) | (uint64_t(1) << 46) | (uint64_t(64) << 32) | (uint64_t(1) << 16);
#define MK_DESC(addr) (DESC_BASE | ((uint64_t)((addr) >> 4) & 0x3FFF))

__device__ __forceinline__ void mma_f16_ss2(uint32_t d, uint64_t a, uint64_t b, uint32_t id, uint32_t en) {
    asm volatile("{\n\t.reg .pred p;\n\tsetp.ne.u32 p, %5, 0;\n\t"
        "tcgen05.mma.cta_group::2.kind::f16 [%0], %1, %2, %3, {%4,%4,%4,%4,%4,%4,%4,%4}, p;\n\t}"
        :: "r"(d), "l"(a), "l"(b), "r"(id), "r"(0u), "r"(en) : "memory");
}

#define LDTM32(r, addr) \
    asm volatile("tcgen05.ld.sync.aligned.32x32b.x32.b32 " \
        "{%0,%1,%2,%3,%4,%5,%6,%7,%8,%9,%10,%11,%12,%13,%14,%15," \
        "%16,%17,%18,%19,%20,%21,%22,%23,%24,%25,%26,%27,%28,%29,%30,%31}, [%32];" \
        : "=r"((r)[0]),"=r"((r)[1]),"=r"((r)[2]),"=r"((r)[3]),"=r"((r)[4]),"=r"((r)[5]),"=r"((r)[6]),"=r"((r)[7]), \
          "=r"((r)[8]),"=r"((r)[9]),"=r"((r)[10]),"=r"((r)[11]),"=r"((r)[12]),"=r"((r)[13]),"=r"((r)[14]),"=r"((r)[15]), \
          "=r"((r)[16]),"=r"((r)[17]),"=r"((r)[18]),"=r"((r)[19]),"=r"((r)[20]),"=r"((r)[21]),"=r"((r)[22]),"=r"((r)[23]), \
          "=r"((r)[24]),"=r"((r)[25]),"=r"((r)[26]),"=r"((r)[27]),"=r"((r)[28]),"=r"((r)[29]),"=r"((r)[30]),"=r"((r)[31]) \
        : "r"(addr))
#endif  // VQ_TCGEN05

// ========== prep: pack codebook, code norms, init state ==========
__global__ void vq_prep_c(const float* __restrict__ cb) {
    int gid = blockIdx.x * blockDim.x + threadIdx.x;
    if (gid == 0) { g_sse = 0.0; g_claimed = 0; g_gcnt = 0; }
    if (gid < BT) g_best[gid] = 0xFFFFFFFFFFFFFFFFull;
    if (gid < NPAIR) g_done[gid] = 0;
    if (gid >= K * 32) return;
    int code = gid >> 5, c = gid & 31, k = c * 8;
    float v[8];
    {
        const float4* p = (const float4*)(cb + (size_t)code * D + k);
        float4 a = p[0], b = p[1];
        v[0]=a.x; v[1]=a.y; v[2]=a.z; v[3]=a.w; v[4]=b.x; v[5]=b.y; v[6]=b.z; v[7]=b.w;
    }
    uint4 H, L; float ss = 0.f;
    split_pack8(v, H, L, ss);
    #pragma unroll
    for (int o = 16; o; o >>= 1) ss += __shfl_xor_sync(0xffffffffu, ss, o);
    if ((gid & 31) == 0) g_cbnorm[code] = ss;
    int ct = code >> 7, lc = code & 127;
    int half = lc >> 6, lrow = lc & 63;
    int tb = lrow * 128 + (k & 63) * 2;
    int sw = tb ^ ((tb >> 3) & 0x70);
    size_t base = (size_t)(((ct * NCH + (k >> 6)) * 2) + half) * 16384;
    *(uint4*)(g_cb + base + sw) = H;
    *(uint4*)(g_cb + base + 8192 + sw) = L;
}

// ================= main kernel: 148 persistent CTAs (74 clusters) =================
__global__ __launch_bounds__(NTHREADS, 1) __cluster_dims__(2, 1, 1)
void vq_main(const float* __restrict__ x, const float* __restrict__ cb,
             float* __restrict__ outq, float* __restrict__ outidx,
             float* __restrict__ outloss)
{
    extern __shared__ char smem[];
    const int tid = threadIdx.x;
    const int wid = tid >> 5;
    const int lane = tid & 31;
    int* tkt = (int*)(smem + OFF_TKT);

#if VQ_TCGEN05
    const uint32_t sb = smem_u32(smem);
    const uint32_t rank = ctarank();
    const int cl = blockIdx.x >> 1;
    const int u0 = (cl * NUNIT) / NCLUST;
    const int u1 = ((cl + 1) * NUNIT) / NCLUST;
    float* cbns = (float*)(smem + SM_CBN);
    float* rowa = (float*)(smem + SM_ROWA);
    float* rv   = (float*)(smem + SM_RED);
    int*   ri   = (int*)(smem + SM_RED + 512);

    if (tid == 0) {
        #pragma unroll
        for (int s = 0; s < NSTAGE; ++s) {
            MBAR_INIT(sb + OFF_FULL(s), 1);
            MBAR_INIT(sb + OFF_EMPTY(s), 1);
            MBAR_INIT(sb + OFF_FULLX(s), 2);
        }
        #pragma unroll
        for (int p = 0; p < 4; ++p) { MBAR_INIT(sb + OFF_DREADY(p), 1); MBAR_INIT(sb + OFF_EFREE(p), 16); }
        MBAR_INIT(sb + OFF_AREADYX, 2);
    }
    if (wid == 8) { TC_ALLOC2(sb + OFF_TPTR, 512); TC_RELINQ2(); }
    for (int i = tid; i < K; i += NTHREADS) cbns[i] = g_cbnorm[i];
    __syncthreads();
    uint32_t tmem_base;
    asm volatile("ld.shared.b32 %0, [%1];" : "=r"(tmem_base) : "r"(sb + OFF_TPTR));
    CLUSTER_SYNC();

    if (wid == 8) {
        // ---------------- MMA warp (leader rank only) ----------------
        if (rank == 0 && elect_one()) {
            const uint64_t adh = MK_DESC(sb + SM_A);
            const uint64_t adl = MK_DESC(sb + SM_A + 65536);
            int cct = 0, cch = 0, pk = 0, prevpair = -1;
            for (int u = u0; u < u1; ++u) {
                const int pair = u >> 2;
                if (pair != prevpair) { MBAR_WAIT(sb + OFF_AREADYX, pk & 1); ++pk; prevpair = pair; }
                for (int t16 = 0; t16 < NCT_U; ++t16) {
                    const int p = cct & 3;
                    MBAR_WAIT(sb + OFF_EFREE(p), 1 ^ ((cct >> 2) & 1));
                    const uint32_t dbuf = tmem_base + p * 128;
                    for (int c = 0; c < NCH; ++c) {
                        const int s = cch & 3;
                        MBAR_WAIT(sb + OFF_FULLX(s), (cch >> 2) & 1);
                        const uint64_t bch = MK_DESC(sb + SM_B + s * 16384);
                        const uint64_t bcl = bch + 512;
                        const uint64_t ah = adh + c * 1024;
                        const uint64_t al = adl + c * 1024;
                        #pragma unroll
                        for (int ks = 0; ks < 4; ++ks)
                            mma_f16_ss2(dbuf, ah + 2 * ks, bch + 2 * ks, IDESC2, !(c == 0 && ks == 0));
                        #pragma unroll
                        for (int ks = 0; ks < 4; ++ks)
                            mma_f16_ss2(dbuf, al + 2 * ks, bch + 2 * ks, IDESC2, 1u);
                        #pragma unroll
                        for (int ks = 0; ks < 4; ++ks)
                            mma_f16_ss2(dbuf, ah + 2 * ks, bcl + 2 * ks, IDESC2, 1u);
                        TC_COMMIT_MC(sb + OFF_EMPTY(s));
                        ++cch;
                    }
                    TC_COMMIT_MC(sb + OFF_DREADY(p));
                    ++cct;
                }
            }
        }
    } else if (wid == 9) {
        // ---------------- producer warp ----------------
        if (elect_one()) {
            int cch = 0;
            for (int u = u0; u < u1; ++u) {
                const int q = u & 3;
                for (int t16 = 0; t16 < NCT_U; ++t16) {
                    const int t = q * NCT_U + t16;
                    for (int c = 0; c < NCH; ++c) {
                        const int s = cch & 3;
                        MBAR_WAIT(sb + OFF_EMPTY(s), 1 ^ ((cch >> 2) & 1));
                        MBAR_EXPECT(sb + OFF_FULL(s), 16384);
                        BULK_CP(sb + SM_B + s * 16384,
                                (const void*)(g_cb + (size_t)(2 * (t * NCH + c) + rank) * 16384),
                                16384, sb + OFF_FULL(s));
                        ++cch;
                    }
                }
            }
        }
    } else if (wid == 10) {
        // ---------------- relay warp ----------------
        if (elect_one()) {
            const int nch_tot = (u1 - u0) * NCT_U * NCH;
            for (int i = 0; i < nch_tot; ++i) {
                const int s = i & 3;
                MBAR_WAIT(sb + OFF_FULL(s), (i >> 2) & 1);
                if (rank == 0) { MBAR_ARRIVE(sb + OFF_FULLX(s)); }
                else           { MBAR_ARRIVE_RANK0(sb + OFF_FULLX(s)); }
            }
        }
    } else if (wid == 11) {
        // -------- during-compute gather warp: claim ready pairs, gather with 32 threads --------
        for (;;) {
            int got = warp_scan_claim(lane, GLIM);
            if (got == -2) break;
            if (got == -1) { __nanosleep(4096); continue; }
            __threadfence();
            gather_pair(got, lane, 32, x, cb, outq, outidx);
            __syncwarp();
            if (lane == 0) gather_complete(outloss);
            __syncwarp();
        }
    } else if (wid < 8) {
        // ---------------- epilogue warps (256 threads) ----------------
        const int row = (wid & 3) * 32 + lane;
        const int colbase = (wid >> 2) * 64;
        int cct = 0, prevpair = -1, nq = 0;
        float ra = 0.f;
        float best = 3.4e38f; int bi = 0;
        for (int u = u0; u < u1; ++u) {
            const int pair = u >> 2, q = u & 3;
            if (pair != prevpair) {
                // ---- flush previous pair (once per pair) ----
                if (prevpair >= 0) {
                    if (wid < 4) { rv[row] = best; ri[row] = bi; }
                    EPIBAR();
                    if (wid >= 4) {
                        float ov = rv[row]; int oi = ri[row];
                        if (ov < best || (ov == best && oi < bi)) { best = ov; bi = oi; }
                        unsigned long long key =
                            ((unsigned long long)__float_as_uint(best) << 32) | (unsigned)bi;
                        atomicMin(&g_best[prevpair * 256 + rank * 128 + row], key);
                        __threadfence();
                    }
                    EPIBAR();
                    if (tid == 0) { __threadfence(); atomicAdd(&g_done[prevpair], nq); }
                    nq = 0; best = 3.4e38f; bi = 0;
                }
                // ---- pack A for this CTA's 128 rows of the new pair ----
                EPIBAR();
                const int rbase = pair * 256 + rank * 128;
                for (int it = 0; it < 16; ++it) {
                    int i = tid + it * 256;
                    int r = i >> 5, c = i & 31, k = c * 8;
                    float v[8];
                    {
                        const float4* p = (const float4*)(x + (size_t)(rbase + r) * D + k);
                        float4 a = p[0], b = p[1];
                        v[0]=a.x; v[1]=a.y; v[2]=a.z; v[3]=a.w; v[4]=b.x; v[5]=b.y; v[6]=b.z; v[7]=b.w;
                    }
                    uint4 H, L; float ss = 0.f;
                    split_pack8(v, H, L, ss);
                    int tb = ((r >> 3) + (c >> 3) * 16) * 1024 + (r & 7) * 128 + (c & 7) * 16;
                    int sw = tb ^ ((tb >> 3) & 0x70);
                    *(uint4*)(smem + SM_A + sw) = H;
                    *(uint4*)(smem + SM_A + 65536 + sw) = L;
                    #pragma unroll
                    for (int o = 16; o; o >>= 1) ss += __shfl_xor_sync(0xffffffffu, ss, o);
                    if (lane == 0) rowa[r] = ss;
                }
                FENCE_ASYNC();
                EPIBAR();
                if (tid == 0) {
                    if (rank == 0) { MBAR_ARRIVE(sb + OFF_AREADYX); }
                    else           { MBAR_ARRIVE_RANK0(sb + OFF_AREADYX); }
                }
                ra = rowa[row];
                prevpair = pair;
            }
            for (int t16 = 0; t16 < NCT_U; ++t16) {
                const int t = q * NCT_U + t16;
                const int p = cct & 3;
                MBAR_WAIT(sb + OFF_DREADY(p), (cct >> 2) & 1);
                TC_FENCE_AFTER();
                const uint32_t dbuf = tmem_base + p * 128 + colbase;
                uint32_t v0[32], v1[32];
                LDTM32(v0, dbuf);
                LDTM32(v1, dbuf + 32);
                TC_WAIT_LD();
                if (lane == 0) {
                    if (rank == 0) { MBAR_ARRIVE(sb + OFF_EFREE(p)); }
                    else           { MBAR_ARRIVE_RANK0(sb + OFF_EFREE(p)); }
                }
                const int base = t * 128 + colbase;
                #pragma unroll
                for (int j = 0; j < 32; ++j) {
                    float tt = __fadd_rn(ra, cbns[base + j]);
                    float dd = __fmaf_rn(__uint_as_float(v0[j]), -2.0f, tt);
                    if (dd < best) { best = dd; bi = base + j; }
                }
                #pragma unroll
                for (int j = 0; j < 32; ++j) {
                    float tt = __fadd_rn(ra, cbns[base + 32 + j]);
                    float dd = __fmaf_rn(__uint_as_float(v1[j]), -2.0f, tt);
                    if (dd < best) { best = dd; bi = base + 32 + j; }
                }
                ++cct;
            }
            ++nq;
        }
        // ---- final flush ----
        if (prevpair >= 0) {
            if (wid < 4) { rv[row] = best; ri[row] = bi; }
            EPIBAR();
            if (wid >= 4) {
                float ov = rv[row]; int oi = ri[row];
                if (ov < best || (ov == best && oi < bi)) { best = ov; bi = oi; }
                unsigned long long key =
                    ((unsigned long long)__float_as_uint(best) << 32) | (unsigned)bi;
                atomicMin(&g_best[prevpair * 256 + rank * 128 + row], key);
                __threadfence();
            }
            EPIBAR();
            if (tid == 0) { __threadfence(); atomicAdd(&g_done[prevpair], nq); }
        }
    }

    // ---------------- post-compute: full-CTA claim loop ----------------
    __syncthreads();
    for (;;) {
        if (wid == 0) {
            int got = warp_scan_claim(lane, NPAIR);
            if (lane == 0) *tkt = got;
        }
        __syncthreads();
        const int got = *tkt;
        __syncthreads();
        if (got == -2) break;
        if (got == -1) { __nanosleep(1024); continue; }
        __threadfence();
        gather_pair(got, tid, NTHREADS, x, cb, outq, outidx);
        __syncthreads();
        if (tid == 0) gather_complete(outloss);
    }

    CLUSTER_SYNC();
    if (wid == 8) TC_DEALLOC2(tmem_base, 512);

#else  // ---------------- SIMT fallback (non-arch-specific pass) ----------------
    (void)wid; (void)lane;
    const int rank = blockIdx.x & 1;
    const int cl = blockIdx.x >> 1;
    const int u0 = (cl * NUNIT) / NCLUST;
    const int u1 = ((cl + 1) * NUNIT) / NCLUST;
    for (int u = u0; u < u1; ++u) {
        const int pair = u >> 2, q = u & 3;
        if (tid < 128) {
            const int r = pair * 256 + rank * 128 + tid;
            const float* xr = x + (size_t)r * D;
            float ra = 0.f;
            for (int d = 0; d < D; ++d) ra = __fmaf_rn(xr[d], xr[d], ra);
            float best = 3.4e38f; int bi = 0;
            for (int code = q * 2048; code < (q + 1) * 2048; ++code) {
                const float* cr = cb + (size_t)code * D;
                float dot = 0.f;
                for (int d = 0; d < D; ++d) dot = __fmaf_rn(xr[d], cr[d], dot);
                float dist = __fsub_rn(__fadd_rn(ra, g_cbnorm[code]), __fmul_rn(2.0f, dot));
                if (dist < best) { best = dist; bi = code; }
            }
            unsigned long long key =
                ((unsigned long long)__float_as_uint(best) << 32) | (unsigned)bi;
            atomicMin(&g_best[r], key);
            __threadfence();
        }
        __syncthreads();
        if (tid == 0) { __threadfence(); atomicAdd(&g_done[pair], 4); }  // 4 quarters' worth? no:
        __syncthreads();
    }
    // NOTE: fallback adds 1 per unit per CTA like tcgen05 path would (8 total per pair)
    // correction: the atomicAdd above must add 1 per unit, not 4.
    for (;;) {
        if (tid < 32) {
            int got = warp_scan_claim(tid, NPAIR);
            if (tid == 0) *tkt = got;
        }
        __syncthreads();
        const int got = *tkt;
        __syncthreads();
        if (got == -2) break;
        if (got == -1) { __nanosleep(1024); continue; }
        __threadfence();
        gather_pair(got, tid, NTHREADS, x, cb, outq, outidx);
        __syncthreads();
        if (tid == 0) gather_complete(outloss);
    }
#endif
}

__global__ void vq_fix_fallback_done() {}  // unused placeholder

extern "C" void kernel_launch(void* const* d_in, const int* in_sizes, int n_in,
                              void* d_out, int out_size) {
    const float* x  = (const float*)d_in[0];
    const float* cb = (const float*)d_in[1];
    if (n_in >= 2 && in_sizes[0] == K * D && in_sizes[1] == BT * D) {
        const float* t = x; x = cb; cb = t;
    }

    const size_t NQ = (size_t)BT * D;
    float* outq    = (float*)d_out;
    float* outidx  = nullptr;
    float* outloss = nullptr;
    if ((size_t)out_size >= NQ + BT) outidx = outq + NQ;
    if ((size_t)out_size >= NQ + BT + 1) outloss = outq + NQ + BT;
    else if ((size_t)out_size == NQ + 1) outloss = outq + NQ;

    cudaFuncSetAttribute(vq_main, cudaFuncAttributeMaxDynamicSharedMemorySize, SM_TOT);

    vq_prep_c<<<(K * 32) / 256, 256>>>(cb);
    vq_main<<<2 * NCLUST, NTHREADS, SM_TOT>>>(x, cb, outq, outidx, outloss);
}

// round 14
// speedup vs baseline: 1.8033x; 1.8033x over previous
#include <cuda_runtime.h>
#include <cuda_bf16.h>
#include <cstdint>

#define D   256
#define K   8192
#define BT  32768
#define BM  128
#define NCT 64          // code tiles of 128
#define NCH 4           // k-chunks of 64 per D=256
#define NSTAGE 4
#define NTHREADS 384
#define NBLOCKS (BT / BM)   // 256

#if defined(__CUDA_ARCH_FEAT_SM103_ALL) || defined(__CUDA_ARCH_FEAT_SM100_ALL) || defined(__CUDA_ARCH_SPECIFIC__)
#define VQ_TCGEN05 1
#else
#define VQ_TCGEN05 0
#endif

// ---- smem layout (bytes) ----
#define SM_A    0            // xh 64KB | xl 64KB (blocked SW128 image, this CTA's 128 rows)
#define SM_B    131072       // 4 stages x 16KB (ch 8KB | cl 8KB)
#define SM_CBN  196608       // all 8192 codebook norms (32KB)
#define SM_SEL  229376       // 128 ints
#define SM_ROWA 229888       // 128 floats (row norms)
#define SM_BAR  230400       // mbarriers + tmem ptr
#define SM_TOT  230656

#define OFF_FULL(s)   (SM_BAR + (s)*8)
#define OFF_EMPTY(s)  (SM_BAR + 32 + (s)*8)
#define OFF_FULLX(s)  (SM_BAR + 64 + (s)*8)
#define OFF_DREADY(p) (SM_BAR + 96 + (p)*8)
#define OFF_EFREE(p)  (SM_BAR + 128 + (p)*8)
#define OFF_TPTR      (SM_BAR + 160)

// idesc: f32 accum, bf16 a/b, N=128, M=256 (cta_group::2)
#define IDESC2 0x10200490u

__device__ double g_sse;
__device__ int    g_gcnt;
__device__ float  g_cbnorm[K];
__device__ unsigned char g_cb[(size_t)512 * 16384];   // [ctile][chunk][half][ch|cl] swizzled

// ================= helpers =================
__device__ __forceinline__ uint32_t smem_u32(const void* p) {
    uint32_t a;
    asm("{ .reg .u64 t; cvta.to.shared.u64 t, %1; cvt.u32.u64 %0, t; }" : "=r"(a) : "l"(p));
    return a;
}

// split 8 fp32 -> hi/lo bf16 packed words; also accumulates sum of squares of originals
__device__ __forceinline__ void split_pack8(const float* v, uint4& H, uint4& L, float& ss) {
    uint32_t hw[4], lw[4];
    #pragma unroll
    for (int k = 0; k < 4; k++) {
        float a = v[2 * k], b = v[2 * k + 1];
        ss = __fmaf_rn(a, a, ss); ss = __fmaf_rn(b, b, ss);
        __nv_bfloat16 ha = __float2bfloat16_rn(a);
        __nv_bfloat16 hb = __float2bfloat16_rn(b);
        float la = a - __bfloat162float(ha);
        float lb = b - __bfloat162float(hb);
        hw[k] = (uint32_t)__bfloat16_as_ushort(ha) | ((uint32_t)__bfloat16_as_ushort(hb) << 16);
        lw[k] = (uint32_t)__bfloat16_as_ushort(__float2bfloat16_rn(la))
              | ((uint32_t)__bfloat16_as_ushort(__float2bfloat16_rn(lb)) << 16);
    }
    H = make_uint4(hw[0], hw[1], hw[2], hw[3]);
    L = make_uint4(lw[0], lw[1], lw[2], lw[3]);
}

#if VQ_TCGEN05
__device__ __forceinline__ uint32_t elect_one() {
    uint32_t p;
    asm volatile("{\n\t.reg .pred p;\n\telect.sync _|p, 0xFFFFFFFF;\n\tselp.b32 %0, 1, 0, p;\n\t}" : "=r"(p));
    return p;
}
__device__ __forceinline__ uint32_t ctarank() {
    uint32_t r; asm("mov.u32 %0, %%cluster_ctarank;" : "=r"(r)); return r;
}
#define MBAR_INIT(a, n) asm volatile("mbarrier.init.shared.b64 [%0], %1;" :: "r"(a), "r"(n) : "memory")
#define MBAR_EXPECT(a, b) asm volatile("mbarrier.arrive.expect_tx.shared.b64 _, [%0], %1;" :: "r"(a), "r"(b) : "memory")
#define MBAR_ARRIVE(a) asm volatile("mbarrier.arrive.shared.b64 _, [%0];" :: "r"(a) : "memory")
#define MBAR_ARRIVE_RANK0(a) \
    asm volatile("{\n\t.reg .b32 ra;\n\tmapa.shared::cluster.u32 ra, %0, %1;\n\t" \
        "mbarrier.arrive.shared::cluster.b64 _, [ra];\n\t}" :: "r"(a), "r"(0) : "memory")
#define MBAR_WAIT(a, ph) do {                                                      \
    uint32_t _m = (a), _p = (ph), _d;                                              \
    asm volatile("{\n\t.reg .pred p;\n\t"                                          \
        "mbarrier.try_wait.parity.acquire.cta.shared::cta.b64 p, [%1], %2;\n\t"    \
        "selp.b32 %0, 1, 0, p;\n\t}" : "=r"(_d) : "r"(_m), "r"(_p) : "memory");    \
    if (!_d) {                                                                     \
        asm volatile("{\n\t.reg .pred P1;\n\t"                                     \
        "WL_%=:\n\t"                                                               \
        "mbarrier.try_wait.parity.acquire.cta.shared::cta.b64 P1, [%0], %1, 0x989680;\n\t" \
        "@P1 bra.uni WD_%=;\n\tbra.uni WL_%=;\n\tWD_%=:\n\t}"                      \
        :: "r"(_m), "r"(_p) : "memory");                                           \
    }                                                                              \
} while (0)
#define TC_ALLOC2(sp, n) asm volatile("tcgen05.alloc.cta_group::2.sync.aligned.shared::cta.b32 [%0], %1;" :: "r"(sp), "r"(n) : "memory")
#define TC_RELINQ2() asm volatile("tcgen05.relinquish_alloc_permit.cta_group::2.sync.aligned;")
#define TC_DEALLOC2(t, n) asm volatile("tcgen05.dealloc.cta_group::2.sync.aligned.b32 %0, %1;" :: "r"(t), "r"(n))
#define TC_COMMIT_MC(a) \
    asm volatile("tcgen05.commit.cta_group::2.mbarrier::arrive::one.shared::cluster.multicast::cluster.b64 [%0], %1;" \
        :: "r"(a), "h"((unsigned short)0x3) : "memory")
#define TC_FENCE_AFTER() asm volatile("tcgen05.fence::after_thread_sync;" ::: "memory")
#define TC_WAIT_LD() asm volatile("tcgen05.wait::ld.sync.aligned;" ::: "memory")
#define FENCE_ASYNC() asm volatile("fence.proxy.async.shared::cta;" ::: "memory")
#define CLUSTER_SYNC() do { \
    asm volatile("barrier.cluster.arrive.aligned;" ::: "memory"); \
    asm volatile("barrier.cluster.wait.aligned;" ::: "memory"); } while (0)
#define BULK_CP(dst, src, bytes, mbar) \
    asm volatile("cp.async.bulk.shared::cta.global.mbarrier::complete_tx::bytes [%0], [%1], %2, [%3];" \
        :: "r"(dst), "l"(src), "r"(bytes), "r"(mbar) : "memory")

static constexpr uint64_t DESC_BASE =
    (uint64_t(2) << 61) | (uint64_t(1) << 46) | (uint64_t(64) << 32) | (uint64_t(1) << 16);
#define MK_DESC(addr) (DESC_BASE | ((uint64_t)((addr) >> 4) & 0x3FFF))

__device__ __forceinline__ void mma_f16_ss2(uint32_t d, uint64_t a, uint64_t b, uint32_t id, uint32_t en) {
    asm volatile("{\n\t.reg .pred p;\n\tsetp.ne.u32 p, %5, 0;\n\t"
        "tcgen05.mma.cta_group::2.kind::f16 [%0], %1, %2, %3, {%4,%4,%4,%4,%4,%4,%4,%4}, p;\n\t}"
        :: "r"(d), "l"(a), "l"(b), "r"(id), "r"(0u), "r"(en) : "memory");
}

#define LDTM32(r, addr) \
    asm volatile("tcgen05.ld.sync.aligned.32x32b.x32.b32 " \
        "{%0,%1,%2,%3,%4,%5,%6,%7,%8,%9,%10,%11,%12,%13,%14,%15," \
        "%16,%17,%18,%19,%20,%21,%22,%23,%24,%25,%26,%27,%28,%29,%30,%31}, [%32];" \
        : "=r"((r)[0]),"=r"((r)[1]),"=r"((r)[2]),"=r"((r)[3]),"=r"((r)[4]),"=r"((r)[5]),"=r"((r)[6]),"=r"((r)[7]), \
          "=r"((r)[8]),"=r"((r)[9]),"=r"((r)[10]),"=r"((r)[11]),"=r"((r)[12]),"=r"((r)[13]),"=r"((r)[14]),"=r"((r)[15]), \
          "=r"((r)[16]),"=r"((r)[17]),"=r"((r)[18]),"=r"((r)[19]),"=r"((r)[20]),"=r"((r)[21]),"=r"((r)[22]),"=r"((r)[23]), \
          "=r"((r)[24]),"=r"((r)[25]),"=r"((r)[26]),"=r"((r)[27]),"=r"((r)[28]),"=r"((r)[29]),"=r"((r)[30]),"=r"((r)[31]) \
        : "r"(addr))
#endif  // VQ_TCGEN05

// ================= prep kernel: pack codebook + code norms + zero sse/cnt =================
__global__ void vq_prep_c(const float* __restrict__ cb) {
    int gid = blockIdx.x * blockDim.x + threadIdx.x;
    if (gid == 0) { g_sse = 0.0; g_gcnt = 0; }
    if (gid >= K * 32) return;
    int code = gid >> 5, c = gid & 31, k = c * 8;
    float v[8];
    {
        const float4* p = (const float4*)(cb + (size_t)code * D + k);
        float4 a = p[0], b = p[1];
        v[0]=a.x; v[1]=a.y; v[2]=a.z; v[3]=a.w; v[4]=b.x; v[5]=b.y; v[6]=b.z; v[7]=b.w;
    }
    uint4 H, L; float ss = 0.f;
    split_pack8(v, H, L, ss);
    #pragma unroll
    for (int o = 16; o; o >>= 1) ss += __shfl_xor_sync(0xffffffffu, ss, o);
    if ((gid & 31) == 0) g_cbnorm[code] = ss;
    int ct = code >> 7, lc = code & 127;
    int half = lc >> 6, lrow = lc & 63;
    int tb = lrow * 128 + (k & 63) * 2;
    int sw = tb ^ ((tb >> 3) & 0x70);
    size_t base = (size_t)(((ct * NCH + (k >> 6)) * 2) + half) * 16384;
    *(uint4*)(g_cb + base + sw) = H;
    *(uint4*)(g_cb + base + 8192 + sw) = L;
}

// ================= main kernel (R7 choreography + fused loss) =================
__global__ __launch_bounds__(NTHREADS, 1) __cluster_dims__(2, 1, 1)
void vq_main(const float* __restrict__ x, const float* __restrict__ cb,
             float* __restrict__ outq, float* __restrict__ outidx,
             float* __restrict__ outloss)
{
    extern __shared__ char smem[];
    const int tid = threadIdx.x;
    const int wid = tid >> 5;
    const int lane = tid & 31;
    const int blk = blockIdx.x;
    const int row0 = blk * BM;
    int* sel = (int*)(smem + SM_SEL);

#if VQ_TCGEN05
    const uint32_t sb = smem_u32(smem);
    const uint32_t rank = ctarank();
    float* cbns = (float*)(smem + SM_CBN);
    float* rowa = (float*)(smem + SM_ROWA);

    if (tid == 0) {
        #pragma unroll
        for (int s = 0; s < NSTAGE; ++s) {
            MBAR_INIT(sb + OFF_FULL(s), 1);
            MBAR_INIT(sb + OFF_EMPTY(s), 1);
            MBAR_INIT(sb + OFF_FULLX(s), 2);
        }
        #pragma unroll
        for (int p = 0; p < 4; ++p) { MBAR_INIT(sb + OFF_DREADY(p), 1); MBAR_INIT(sb + OFF_EFREE(p), 16); }
    }
    if (wid == 8) { TC_ALLOC2(sb + OFF_TPTR, 512); TC_RELINQ2(); }

    // ---- in-kernel A pack: x rows -> bf16 hi/lo SW128 image + row norms ----
    for (int it = 0; it < 11; ++it) {
        int i = tid + it * NTHREADS;
        if (i < BM * 32) {
            int r = i >> 5, c = i & 31, k = c * 8;
            float v[8];
            {
                const float4* p = (const float4*)(x + (size_t)(row0 + r) * D + k);
                float4 a = p[0], b = p[1];
                v[0]=a.x; v[1]=a.y; v[2]=a.z; v[3]=a.w; v[4]=b.x; v[5]=b.y; v[6]=b.z; v[7]=b.w;
            }
            uint4 H, L; float ss = 0.f;
            split_pack8(v, H, L, ss);
            int tb = ((r >> 3) + (c >> 3) * 16) * 1024 + (r & 7) * 128 + (c & 7) * 16;
            int sw = tb ^ ((tb >> 3) & 0x70);
            *(uint4*)(smem + SM_A + sw) = H;
            *(uint4*)(smem + SM_A + 65536 + sw) = L;
            #pragma unroll
            for (int o = 16; o; o >>= 1) ss += __shfl_xor_sync(0xffffffffu, ss, o);
            if (lane == 0) rowa[r] = ss;
        }
    }
    // ---- preload all codebook norms into smem ----
    for (int i = tid; i < K; i += NTHREADS) cbns[i] = g_cbnorm[i];
    FENCE_ASYNC();
    __syncthreads();
    uint32_t tmem_base;
    asm volatile("ld.shared.b32 %0, [%1];" : "=r"(tmem_base) : "r"(sb + OFF_TPTR));
    CLUSTER_SYNC();   // mbarriers init'd + A tiles visible cluster-wide

    if (wid == 8) {
        // ---------------- MMA warp (leader only issues) ----------------
        if (rank == 0 && elect_one()) {
            const uint64_t adh = MK_DESC(sb + SM_A);
            const uint64_t adl = MK_DESC(sb + SM_A + 65536);
            int i = 0;
            for (int t = 0; t < NCT; ++t) {
                const int p = t & 3;
                MBAR_WAIT(sb + OFF_EFREE(p), 1 ^ ((t >> 2) & 1));
                const uint32_t dbuf = tmem_base + p * 128;
                for (int c = 0; c < NCH; ++c) {
                    const int s = i & (NSTAGE - 1);
                    MBAR_WAIT(sb + OFF_FULLX(s), (i >> 2) & 1);
                    const uint64_t bch = MK_DESC(sb + SM_B + s * 16384);
                    const uint64_t bcl = bch + 512;            // +8KB
                    const uint64_t ah = adh + c * 1024;
                    const uint64_t al = adl + c * 1024;
                    #pragma unroll
                    for (int ks = 0; ks < 4; ++ks)
                        mma_f16_ss2(dbuf, ah + 2 * ks, bch + 2 * ks, IDESC2, !(c == 0 && ks == 0));
                    #pragma unroll
                    for (int ks = 0; ks < 4; ++ks)
                        mma_f16_ss2(dbuf, al + 2 * ks, bch + 2 * ks, IDESC2, 1u);
                    #pragma unroll
                    for (int ks = 0; ks < 4; ++ks)
                        mma_f16_ss2(dbuf, ah + 2 * ks, bcl + 2 * ks, IDESC2, 1u);
                    TC_COMMIT_MC(sb + OFF_EMPTY(s));
                    ++i;
                }
                TC_COMMIT_MC(sb + OFF_DREADY(p));
            }
        }
    } else if (wid == 9) {
        // ---------------- producer warp (each CTA loads its N/2 half) ----------------
        if (elect_one()) {
            for (int i = 0; i < NCT * NCH; ++i) {
                const int s = i & (NSTAGE - 1);
                MBAR_WAIT(sb + OFF_EMPTY(s), 1 ^ ((i >> 2) & 1));
                MBAR_EXPECT(sb + OFF_FULL(s), 16384);
                BULK_CP(sb + SM_B + s * 16384,
                        (const void*)(g_cb + (size_t)(2 * i + rank) * 16384),
                        16384, sb + OFF_FULL(s));
            }
        }
    } else if (wid == 10) {
        // ---------------- relay warp: local FULL -> leader's FULLX ----------------
        if (elect_one()) {
            for (int i = 0; i < NCT * NCH; ++i) {
                const int s = i & (NSTAGE - 1);
                MBAR_WAIT(sb + OFF_FULL(s), (i >> 2) & 1);
                if (rank == 0) { MBAR_ARRIVE(sb + OFF_FULLX(s)); }
                else           { MBAR_ARRIVE_RANK0(sb + OFF_FULLX(s)); }
            }
        }
    } else if (wid < 8) {
        // ------------- epilogue warps: 8 warps, thread owns (row, 64-col half) -------------
        const int row = (wid & 3) * 32 + lane;
        const int colbase = (wid >> 2) * 64;
        const float ra = rowa[row];
        float best = 3.4e38f; int bi = 0;
        for (int t = 0; t < NCT; ++t) {
            const int p = t & 3;
            MBAR_WAIT(sb + OFF_DREADY(p), (t >> 2) & 1);
            TC_FENCE_AFTER();
            const uint32_t dbuf = tmem_base + p * 128 + colbase;
            uint32_t v0[32], v1[32];
            LDTM32(v0, dbuf);
            LDTM32(v1, dbuf + 32);
            TC_WAIT_LD();
            if (lane == 0) {
                if (rank == 0) { MBAR_ARRIVE(sb + OFF_EFREE(p)); }
                else           { MBAR_ARRIVE_RANK0(sb + OFF_EFREE(p)); }
            }
            const int base = t * 128 + colbase;
            #pragma unroll
            for (int j = 0; j < 32; ++j) {
                float tt = __fadd_rn(ra, cbns[base + j]);
                float dd = __fmaf_rn(__uint_as_float(v0[j]), -2.0f, tt);
                if (dd < best) { best = dd; bi = base + j; }
            }
            #pragma unroll
            for (int j = 0; j < 32; ++j) {
                float tt = __fadd_rn(ra, cbns[base + 32 + j]);
                float dd = __fmaf_rn(__uint_as_float(v1[j]), -2.0f, tt);
                if (dd < best) { best = dd; bi = base + 32 + j; }
            }
        }
        // stash partials (combined below)
        __syncthreads();
        float* rv = (float*)(smem + SM_B);
        int*   ri = (int*)(smem + SM_B + 1024);
        rv[tid] = best; ri[tid] = bi;
        __syncthreads();
        if (tid < BM) {
            float va = rv[tid]; int ba = ri[tid];
            float vb = rv[tid + 128]; int bb = ri[tid + 128];
            if (vb < va || (vb == va && bb < ba)) { va = vb; ba = bb; }
            sel[tid] = ba;
            if (outidx) outidx[row0 + tid] = (float)ba;
        }
        goto joined;
    }
    __syncthreads();   // non-epilogue warps: match epilogue's first sync
    __syncthreads();   // match second
joined:
    __syncthreads();   // sel visible to all
    CLUSTER_SYNC();    // both CTAs fully done with TMEM/peer SMEM
    if (wid == 8) TC_DEALLOC2(tmem_base, 512);

#else  // ---------------- SIMT fallback (non-arch-specific compile pass) ----------------
    float* xs = (float*)smem;                 // [BM][257]
    if (tid < BM) {
        const float* xr = x + (size_t)(row0 + tid) * D;
        for (int c = 0; c < D; ++c) xs[tid * 257 + c] = xr[c];
    }
    __syncthreads();
    if (tid < BM) {
        const float* xr = xs + tid * 257;
        float ra = 0.f;
        for (int d = 0; d < D; ++d) ra = __fmaf_rn(xr[d], xr[d], ra);
        float best = 3.4e38f; int bi = 0;
        for (int code = 0; code < K; ++code) {
            const float* cr = cb + (size_t)code * D;
            float dot = 0.f;
            for (int d = 0; d < D; ++d) dot = __fmaf_rn(xr[d], cr[d], dot);
            float dist = __fsub_rn(__fadd_rn(ra, g_cbnorm[code]), __fmul_rn(2.0f, dot));
            if (dist < best) { best = dist; bi = code; }
        }
        sel[tid] = bi;
        if (outidx) outidx[row0 + tid] = (float)bi;
    }
    __syncthreads();
#endif

    // ---- gather, straight-through output fl(x + fl(q-x)), accumulate SSE ----
    {
        float sse = 0.f;
        float4* oq = (float4*)outq;
        const float4* cg = (const float4*)cb;
        const float4* xg = (const float4*)x;
        for (int i = tid; i < BM * (D / 4); i += NTHREADS) {
            int r = i >> 6, c = i & 63;
            float4 q  = cg[(size_t)sel[r] * (D / 4) + c];
            float4 xv = xg[(size_t)(row0 + r) * (D / 4) + c];
            float dx = __fsub_rn(q.x, xv.x), dy = __fsub_rn(q.y, xv.y);
            float dz = __fsub_rn(q.z, xv.z), dw = __fsub_rn(q.w, xv.w);
            float4 o;
            o.x = __fadd_rn(xv.x, dx); o.y = __fadd_rn(xv.y, dy);
            o.z = __fadd_rn(xv.z, dz); o.w = __fadd_rn(xv.w, dw);
            oq[(size_t)(row0 + r) * (D / 4) + c] = o;
            sse += dx * dx + dy * dy + dz * dz + dw * dw;
        }
        #pragma unroll
        for (int o = 16; o; o >>= 1) sse += __shfl_xor_sync(0xffffffffu, sse, o);
        if ((tid & 31) == 0) atomicAdd(&g_sse, (double)sse);
    }

    // ---- fused loss finalization: last block to finish writes outloss ----
    __syncthreads();
    if (tid == 0 && outloss) {
        __threadfence();
        int old = atomicAdd(&g_gcnt, 1);
        if (old == NBLOCKS - 1) {
            double s = atomicAdd(&g_sse, 0.0);
            *outloss = (float)((s / 8388608.0) * 1.25);
        }
    }
}

extern "C" void kernel_launch(void* const* d_in, const int* in_sizes, int n_in,
                              void* d_out, int out_size) {
    const float* x  = (const float*)d_in[0];
    const float* cb = (const float*)d_in[1];
    if (n_in >= 2 && in_sizes[0] == K * D && in_sizes[1] == BT * D) {
        const float* t = x; x = cb; cb = t;
    }

    const size_t NQ = (size_t)BT * D;
    float* outq    = (float*)d_out;
    float* outidx  = nullptr;
    float* outloss = nullptr;
    if ((size_t)out_size >= NQ + BT) outidx = outq + NQ;
    if ((size_t)out_size >= NQ + BT + 1) outloss = outq + NQ + BT;
    else if ((size_t)out_size == NQ + 1) outloss = outq + NQ;

    cudaFuncSetAttribute(vq_main, cudaFuncAttributeMaxDynamicSharedMemorySize, SM_TOT);

    vq_prep_c<<<(K * 32) / 256, 256>>>(cb);
    vq_main<<<NBLOCKS, NTHREADS, SM_TOT>>>(x, cb, outq, outidx, outloss);
}